// round 1
// baseline (speedup 1.0000x reference)
#include <cuda_runtime.h>
#include <cstdint>
#include <math.h>

#define EDIM 128
#define BM   128
#define PAD  132   // smem row stride (floats); multiple of 4 for float4 alignment

// dynamic smem layout (floats unless noted):
//   xs   [EDIM][PAD]  : xs[k][r] = x[row0+r][k]
//   cs   [EDIM][PAD]  : cs[k][j] = c[j][k]
//   c_sq [EDIM], x_sq [BM]
//   key  [BM] (u64), s_row [BM] (f32), j_row [BM] (i32)
static constexpr int    SMEM_FLOATS = EDIM * PAD * 2 + EDIM + BM;
static constexpr size_t SMEM_BYTES  = (size_t)SMEM_FLOATS * 4 + (size_t)BM * 8
                                      + (size_t)BM * 4 + (size_t)BM * 4;

__device__ __forceinline__ unsigned long long pack2(float lo, float hi) {
    unsigned long long r;
    asm("mov.b64 %0, {%1, %2};" : "=l"(r) : "f"(lo), "f"(hi));
    return r;
}
__device__ __forceinline__ void fma2(unsigned long long& d,
                                     unsigned long long a, unsigned long long b) {
    asm("fma.rn.f32x2 %0, %1, %2, %0;" : "+l"(d) : "l"(a), "l"(b));
}
__device__ __forceinline__ void unpack2(unsigned long long v, float& lo, float& hi) {
    asm("mov.b64 {%0, %1}, %2;" : "=f"(lo), "=f"(hi) : "l"(v));
}
// order-preserving float -> uint mapping (no NaNs in this data)
__device__ __forceinline__ unsigned int f2ord(float f) {
    unsigned int u = __float_as_uint(f);
    return (u & 0x80000000u) ? ~u : (u | 0x80000000u);
}
__device__ __forceinline__ float ord2f(unsigned int o) {
    unsigned int u = (o & 0x80000000u) ? (o ^ 0x80000000u) : ~o;
    return __uint_as_float(u);
}

__global__ void __launch_bounds__(256, 1)
attractor_kernel(const float* __restrict__ x, const float* __restrict__ c,
                 const float* __restrict__ radii, float* __restrict__ out,
                 int Brows, int write_idx)
{
    extern __shared__ float sm[];
    float* xs   = sm;
    float* cs   = sm + EDIM * PAD;
    float* c_sq = cs + EDIM * PAD;
    float* x_sq = c_sq + EDIM;
    unsigned long long* key = (unsigned long long*)(x_sq + BM);
    float* s_row = (float*)(key + BM);
    int*   j_row = (int*)(s_row + BM);

    const int tid = threadIdx.x;
    const long long row0 = (long long)blockIdx.x * BM;

    if (tid < BM) key[tid] = 0xFFFFFFFFFFFFFFFFull;

    // ---- load c transposed into smem: cs[k][j] = c[j][k] ----
    for (int t = tid; t < EDIM * EDIM / 4; t += 256) {
        int j  = t >> 5;
        int k4 = (t & 31) << 2;
        float4 v = reinterpret_cast<const float4*>(c)[t];
        cs[(k4 + 0) * PAD + j] = v.x;
        cs[(k4 + 1) * PAD + j] = v.y;
        cs[(k4 + 2) * PAD + j] = v.z;
        cs[(k4 + 3) * PAD + j] = v.w;
    }
    // ---- load x tile transposed: xs[k][r] = x[row0+r][k] ----
    for (int t = tid; t < BM * EDIM / 4; t += 256) {
        int r  = t >> 5;
        int k4 = (t & 31) << 2;
        long long row = row0 + r;
        if (row >= Brows) row = Brows - 1;   // clamp (harmless, writes are guarded)
        float4 v = reinterpret_cast<const float4*>(x + row * EDIM)[t & 31];
        xs[(k4 + 0) * PAD + r] = v.x;
        xs[(k4 + 1) * PAD + r] = v.y;
        xs[(k4 + 2) * PAD + r] = v.z;
        xs[(k4 + 3) * PAD + r] = v.w;
    }
    __syncthreads();

    // ---- row norms: ||c_j||^2 and ||x_r||^2 ----
    if (tid < EDIM) {
        float s = 0.f;
        #pragma unroll 8
        for (int k = 0; k < EDIM; k++) { float v = cs[k * PAD + tid]; s = fmaf(v, v, s); }
        c_sq[tid] = s;
    } else {
        int r = tid - EDIM;
        float s = 0.f;
        #pragma unroll 8
        for (int k = 0; k < EDIM; k++) { float v = xs[k * PAD + r]; s = fmaf(v, v, s); }
        x_sq[r] = s;
    }

    // ---- register-tiled GEMM: dot[r][j] with f32x2 accumulators ----
    const int ty = tid >> 4, tx = tid & 15;
    const int r0 = ty * 8, j0 = tx * 8;

    unsigned long long acc[8][4];
    #pragma unroll
    for (int r = 0; r < 8; r++)
        #pragma unroll
        for (int q = 0; q < 4; q++) acc[r][q] = 0ull;  // (0.f, 0.f)

    #pragma unroll 4
    for (int k = 0; k < EDIM; k++) {
        const float* xr = &xs[k * PAD + r0];
        const float* cr = &cs[k * PAD + j0];
        float4 a0 = *reinterpret_cast<const float4*>(xr);
        float4 a1 = *reinterpret_cast<const float4*>(xr + 4);
        float4 b0 = *reinterpret_cast<const float4*>(cr);
        float4 b1 = *reinterpret_cast<const float4*>(cr + 4);
        unsigned long long bb0 = pack2(b0.x, b0.y), bb1 = pack2(b0.z, b0.w);
        unsigned long long bb2 = pack2(b1.x, b1.y), bb3 = pack2(b1.z, b1.w);
        float av[8] = {a0.x, a0.y, a0.z, a0.w, a1.x, a1.y, a1.z, a1.w};
        #pragma unroll
        for (int r = 0; r < 8; r++) {
            unsigned long long aa = pack2(av[r], av[r]);
            fma2(acc[r][0], aa, bb0);
            fma2(acc[r][1], aa, bb1);
            fma2(acc[r][2], aa, bb2);
            fma2(acc[r][3], aa, bb3);
        }
    }
    __syncthreads();  // c_sq/x_sq ready; all smem tiles stable

    // ---- fused argmin: score = ||c_j||^2 - 2*dot (x_sq is row-constant) ----
    #pragma unroll
    for (int r = 0; r < 8; r++) {
        unsigned long long best = 0xFFFFFFFFFFFFFFFFull;
        #pragma unroll
        for (int q = 0; q < 4; q++) {
            float lo, hi;
            unpack2(acc[r][q], lo, hi);
            int j = j0 + 2 * q;
            float s0 = fmaf(-2.f, lo, c_sq[j]);
            float s1 = fmaf(-2.f, hi, c_sq[j + 1]);
            unsigned long long k0 = ((unsigned long long)f2ord(s0) << 32) | (unsigned)j;
            unsigned long long k1 = ((unsigned long long)f2ord(s1) << 32) | (unsigned)(j + 1);
            unsigned long long m = k0 < k1 ? k0 : k1;
            if (m < best) best = m;
        }
        atomicMin(&key[r0 + r], best);
    }
    __syncthreads();

    // ---- per-row scalar epilogue ----
    if (tid < BM) {
        unsigned long long kk = key[tid];
        int   j     = (int)(kk & 0xFFFFFFFFull);
        float score = ord2f((unsigned int)(kk >> 32));
        float d2    = x_sq[tid] + score;
        float dist  = sqrtf(fmaxf(d2, 0.f));
        float strength = expf(-dist / (radii[j] + 1e-8f));
        s_row[tid] = 0.1f * strength;
        j_row[tid] = j;
        if (write_idx && (row0 + tid) < Brows)
            out[(long long)Brows * EDIM + row0 + tid] = (float)j;
    }
    __syncthreads();

    // ---- write attracted = x*(1-s) + c[idx]*s; one warp writes one row/iter ----
    const int wid = tid >> 5, lane = tid & 31;
    #pragma unroll
    for (int it = 0; it < 16; it++) {
        int r = wid + it * 8;
        long long row = row0 + r;
        if (row >= Brows) continue;
        float s = s_row[r];
        int   j = j_row[r];
        float om = 1.f - s;
        int i = lane * 4;
        float4 v;
        v.x = fmaf(cs[(i + 0) * PAD + j], s, xs[(i + 0) * PAD + r] * om);
        v.y = fmaf(cs[(i + 1) * PAD + j], s, xs[(i + 1) * PAD + r] * om);
        v.z = fmaf(cs[(i + 2) * PAD + j], s, xs[(i + 2) * PAD + r] * om);
        v.w = fmaf(cs[(i + 3) * PAD + j], s, xs[(i + 3) * PAD + r] * om);
        reinterpret_cast<float4*>(out + row * EDIM)[lane] = v;
    }
}

extern "C" void kernel_launch(void* const* d_in, const int* in_sizes, int n_in,
                              void* d_out, int out_size)
{
    const float* x     = (const float*)d_in[0];
    const float* c     = (const float*)d_in[1];
    const float* radii = (const float*)d_in[2];
    float* out = (float*)d_out;

    int Brows = in_sizes[0] / EDIM;
    // outputs are (attracted[B,E], idx[B]) flattened; only write idx if room exists
    int write_idx = (out_size >= Brows * (EDIM + 1)) ? 1 : 0;

    cudaFuncSetAttribute(attractor_kernel,
                         cudaFuncAttributeMaxDynamicSharedMemorySize,
                         (int)SMEM_BYTES);

    int grid = (Brows + BM - 1) / BM;
    attractor_kernel<<<grid, 256, SMEM_BYTES>>>(x, c, radii, out, Brows, write_idx);
}

// round 2
// speedup vs baseline: 1.0101x; 1.0101x over previous
#include <cuda_runtime.h>
#include <cstdint>
#include <math.h>

#define EDIM 128
#define BM   128
#define PAD  132   // smem row stride (floats); multiple of 4 for float4 alignment

// dynamic smem layout (floats unless noted):
//   xs   [EDIM][PAD]  : xs[k][r] = x[row0+r][k]
//   cs   [EDIM][PAD]  : cs[k][j] = c[j][k]
//   c_sq [EDIM], x_sq [BM]
//   key  [BM] (u64), s_row [BM] (f32), j_row [BM] (i32)
static constexpr int    SMEM_FLOATS = EDIM * PAD * 2 + EDIM + BM;
static constexpr size_t SMEM_BYTES  = (size_t)SMEM_FLOATS * 4 + (size_t)BM * 8
                                      + (size_t)BM * 4 + (size_t)BM * 4;

__device__ __forceinline__ unsigned long long pack2(float lo, float hi) {
    unsigned long long r;
    asm("mov.b64 %0, {%1, %2};" : "=l"(r) : "f"(lo), "f"(hi));
    return r;
}
__device__ __forceinline__ void fma2(unsigned long long& d,
                                     unsigned long long a, unsigned long long b) {
    asm("fma.rn.f32x2 %0, %1, %2, %0;" : "+l"(d) : "l"(a), "l"(b));
}
__device__ __forceinline__ void unpack2(unsigned long long v, float& lo, float& hi) {
    asm("mov.b64 {%0, %1}, %2;" : "=f"(lo), "=f"(hi) : "l"(v));
}
// order-preserving float -> uint mapping (no NaNs in this data)
__device__ __forceinline__ unsigned int f2ord(float f) {
    unsigned int u = __float_as_uint(f);
    return (u & 0x80000000u) ? ~u : (u | 0x80000000u);
}
__device__ __forceinline__ float ord2f(unsigned int o) {
    unsigned int u = (o & 0x80000000u) ? (o ^ 0x80000000u) : ~o;
    return __uint_as_float(u);
}

__global__ void __launch_bounds__(256, 1)
attractor_kernel(const float* __restrict__ x, const float* __restrict__ c,
                 const float* __restrict__ radii, float* __restrict__ out,
                 int Brows, int write_idx)
{
    extern __shared__ float sm[];
    float* xs   = sm;
    float* cs   = sm + EDIM * PAD;
    float* c_sq = cs + EDIM * PAD;
    float* x_sq = c_sq + EDIM;
    unsigned long long* key = (unsigned long long*)(x_sq + BM);
    float* s_row = (float*)(key + BM);
    int*   j_row = (int*)(s_row + BM);

    const int tid = threadIdx.x;
    const long long row0 = (long long)blockIdx.x * BM;

    if (tid < BM) key[tid] = 0xFFFFFFFFFFFFFFFFull;

    // ---- load c transposed into smem: cs[k][j] = c[j][k] ----
    for (int t = tid; t < EDIM * EDIM / 4; t += 256) {
        int j  = t >> 5;
        int k4 = (t & 31) << 2;
        float4 v = reinterpret_cast<const float4*>(c)[t];
        cs[(k4 + 0) * PAD + j] = v.x;
        cs[(k4 + 1) * PAD + j] = v.y;
        cs[(k4 + 2) * PAD + j] = v.z;
        cs[(k4 + 3) * PAD + j] = v.w;
    }
    // ---- load x tile transposed: xs[k][r] = x[row0+r][k] ----
    for (int t = tid; t < BM * EDIM / 4; t += 256) {
        int r  = t >> 5;
        int k4 = (t & 31) << 2;
        long long row = row0 + r;
        if (row >= Brows) row = Brows - 1;   // clamp (harmless, writes are guarded)
        float4 v = reinterpret_cast<const float4*>(x + row * EDIM)[t & 31];
        xs[(k4 + 0) * PAD + r] = v.x;
        xs[(k4 + 1) * PAD + r] = v.y;
        xs[(k4 + 2) * PAD + r] = v.z;
        xs[(k4 + 3) * PAD + r] = v.w;
    }
    __syncthreads();

    // ---- row norms: ||c_j||^2 and ||x_r||^2 ----
    if (tid < EDIM) {
        float s = 0.f;
        #pragma unroll 8
        for (int k = 0; k < EDIM; k++) { float v = cs[k * PAD + tid]; s = fmaf(v, v, s); }
        c_sq[tid] = s;
    } else {
        int r = tid - EDIM;
        float s = 0.f;
        #pragma unroll 8
        for (int k = 0; k < EDIM; k++) { float v = xs[k * PAD + r]; s = fmaf(v, v, s); }
        x_sq[r] = s;
    }

    // ---- register-tiled GEMM: dot[r][j] with f32x2 accumulators ----
    const int ty = tid >> 4, tx = tid & 15;
    const int r0 = ty * 8, j0 = tx * 8;

    unsigned long long acc[8][4];
    #pragma unroll
    for (int r = 0; r < 8; r++)
        #pragma unroll
        for (int q = 0; q < 4; q++) acc[r][q] = 0ull;  // (0.f, 0.f)

    #pragma unroll 4
    for (int k = 0; k < EDIM; k++) {
        const float* xr = &xs[k * PAD + r0];
        const float* cr = &cs[k * PAD + j0];
        float4 a0 = *reinterpret_cast<const float4*>(xr);
        float4 a1 = *reinterpret_cast<const float4*>(xr + 4);
        float4 b0 = *reinterpret_cast<const float4*>(cr);
        float4 b1 = *reinterpret_cast<const float4*>(cr + 4);
        unsigned long long bb0 = pack2(b0.x, b0.y), bb1 = pack2(b0.z, b0.w);
        unsigned long long bb2 = pack2(b1.x, b1.y), bb3 = pack2(b1.z, b1.w);
        float av[8] = {a0.x, a0.y, a0.z, a0.w, a1.x, a1.y, a1.z, a1.w};
        #pragma unroll
        for (int r = 0; r < 8; r++) {
            unsigned long long aa = pack2(av[r], av[r]);
            fma2(acc[r][0], aa, bb0);
            fma2(acc[r][1], aa, bb1);
            fma2(acc[r][2], aa, bb2);
            fma2(acc[r][3], aa, bb3);
        }
    }
    __syncthreads();  // c_sq/x_sq ready; all smem tiles stable

    // ---- fused argmin: score = ||c_j||^2 - 2*dot (x_sq is row-constant) ----
    #pragma unroll
    for (int r = 0; r < 8; r++) {
        unsigned long long best = 0xFFFFFFFFFFFFFFFFull;
        #pragma unroll
        for (int q = 0; q < 4; q++) {
            float lo, hi;
            unpack2(acc[r][q], lo, hi);
            int j = j0 + 2 * q;
            float s0 = fmaf(-2.f, lo, c_sq[j]);
            float s1 = fmaf(-2.f, hi, c_sq[j + 1]);
            unsigned long long k0 = ((unsigned long long)f2ord(s0) << 32) | (unsigned)j;
            unsigned long long k1 = ((unsigned long long)f2ord(s1) << 32) | (unsigned)(j + 1);
            unsigned long long m = k0 < k1 ? k0 : k1;
            if (m < best) best = m;
        }
        atomicMin(&key[r0 + r], best);
    }
    __syncthreads();

    // ---- per-row scalar epilogue ----
    if (tid < BM) {
        unsigned long long kk = key[tid];
        int   j     = (int)(kk & 0xFFFFFFFFull);
        float score = ord2f((unsigned int)(kk >> 32));
        float d2    = x_sq[tid] + score;
        float dist  = sqrtf(fmaxf(d2, 0.f));
        float strength = expf(-dist / (radii[j] + 1e-8f));
        s_row[tid] = 0.1f * strength;
        j_row[tid] = j;
        if (write_idx && (row0 + tid) < Brows)
            out[(long long)Brows * EDIM + row0 + tid] = (float)j;
    }
    __syncthreads();

    // ---- write attracted = x*(1-s) + c[idx]*s; one warp writes one row/iter ----
    const int wid = tid >> 5, lane = tid & 31;
    #pragma unroll
    for (int it = 0; it < 16; it++) {
        int r = wid + it * 8;
        long long row = row0 + r;
        if (row >= Brows) continue;
        float s = s_row[r];
        int   j = j_row[r];
        float om = 1.f - s;
        int i = lane * 4;
        float4 v;
        v.x = fmaf(cs[(i + 0) * PAD + j], s, xs[(i + 0) * PAD + r] * om);
        v.y = fmaf(cs[(i + 1) * PAD + j], s, xs[(i + 1) * PAD + r] * om);
        v.z = fmaf(cs[(i + 2) * PAD + j], s, xs[(i + 2) * PAD + r] * om);
        v.w = fmaf(cs[(i + 3) * PAD + j], s, xs[(i + 3) * PAD + r] * om);
        reinterpret_cast<float4*>(out + row * EDIM)[lane] = v;
    }
}

extern "C" void kernel_launch(void* const* d_in, const int* in_sizes, int n_in,
                              void* d_out, int out_size)
{
    const float* x     = (const float*)d_in[0];
    const float* c     = (const float*)d_in[1];
    const float* radii = (const float*)d_in[2];
    float* out = (float*)d_out;

    int Brows = in_sizes[0] / EDIM;
    // outputs are (attracted[B,E], idx[B]) flattened; only write idx if room exists
    int write_idx = (out_size >= Brows * (EDIM + 1)) ? 1 : 0;

    cudaFuncSetAttribute(attractor_kernel,
                         cudaFuncAttributeMaxDynamicSharedMemorySize,
                         (int)SMEM_BYTES);

    int grid = (Brows + BM - 1) / BM;
    attractor_kernel<<<grid, 256, SMEM_BYTES>>>(x, c, radii, out, Brows, write_idx);
}

// round 4
// speedup vs baseline: 1.8766x; 1.8580x over previous
#include <cuda_runtime.h>
#include <cuda_bf16.h>
#include <cstdint>
#include <math.h>

#define EDIM 128

// ---- dynamic smem offsets ----
#define B_HI   0u       // bf16 [n=128][k=128] swizzled, 32768 B
#define B_MID  32768u   // bf16 plane, 32768 B
#define O_CSQ  65536u   // float[128]
#define O_RAD  66048u   // float[128]
#define O_KEYP 66560u   // u64[128][4][2] = 8192 B (reused as csq partials in setup)
#define O_SROW 74752u   // float[128]
#define O_JROW 75264u   // int[128]
#define SMEM_TOTAL 75776u

#define REFINE_T 1e-2f

__device__ __forceinline__ uint32_t smem_u32(const void* p) {
    uint32_t a;
    asm("{ .reg .u64 t; cvta.to.shared.u64 t, %1; cvt.u32.u64 %0, t; }" : "=r"(a) : "l"(p));
    return a;
}
// swizzled byte offset of 16B chunk kc (0..15) in row n of a [128][256B] plane
__device__ __forceinline__ uint32_t bswz(uint32_t n, uint32_t kc) {
    return n * 256u + (((((kc) ^ n) & 7u) | ((kc) & 8u)) << 4);
}
__device__ __forceinline__ uint32_t cvt_hi2(float lo, float hi) {
    uint32_t r;
    asm("cvt.rn.bf16x2.f32 %0, %1, %2;" : "=r"(r) : "f"(hi), "f"(lo));
    return r;
}
__device__ __forceinline__ uint32_t cvt_mid2(float lo, float hi, uint32_t h) {
    float hlo = __uint_as_float(h << 16);
    float hhi = __uint_as_float(h & 0xFFFF0000u);
    return cvt_hi2(lo - hlo, hi - hhi);
}
__device__ __forceinline__ void ldm_x2(uint32_t& r0, uint32_t& r1, uint32_t addr) {
    asm volatile("ldmatrix.sync.aligned.m8n8.x2.shared.b16 {%0,%1}, [%2];"
                 : "=r"(r0), "=r"(r1) : "r"(addr));
}
__device__ __forceinline__ void mma16816(float* d, const uint32_t* a, const uint32_t* b) {
    asm volatile("mma.sync.aligned.m16n8k16.row.col.f32.bf16.bf16.f32 "
                 "{%0,%1,%2,%3}, {%4,%5,%6,%7}, {%8,%9}, {%0,%1,%2,%3};"
                 : "+f"(d[0]), "+f"(d[1]), "+f"(d[2]), "+f"(d[3])
                 : "r"(a[0]), "r"(a[1]), "r"(a[2]), "r"(a[3]), "r"(b[0]), "r"(b[1]));
}
__device__ __forceinline__ uint32_t f2ord(float f) {
    uint32_t u = __float_as_uint(f);
    return (u & 0x80000000u) ? ~u : (u | 0x80000000u);
}
__device__ __forceinline__ float ord2f(uint32_t o) {
    uint32_t u = (o & 0x80000000u) ? (o ^ 0x80000000u) : ~u;
    // NOTE: expression above must not reference u before init; rewritten below
    return __uint_as_float(u);
}
// (clean version; the one above is shadowed out)
__device__ __forceinline__ float ord2f_ok(uint32_t o) {
    uint32_t u = (o & 0x80000000u) ? (o ^ 0x80000000u) : ~o;
    return __uint_as_float(u);
}
__device__ __forceinline__ float exact_d2(const float4* __restrict__ xp,
                                          const float4* __restrict__ cp) {
    float a0 = 0.f, a1 = 0.f;
#pragma unroll 8
    for (int q = 0; q < 32; q++) {
        float4 xv = xp[q], cv = cp[q];
        float t0 = xv.x - cv.x, t1 = xv.y - cv.y;
        float t2 = xv.z - cv.z, t3 = xv.w - cv.w;
        a0 = fmaf(t0, t0, a0); a1 = fmaf(t1, t1, a1);
        a0 = fmaf(t2, t2, a0); a1 = fmaf(t3, t3, a1);
    }
    return a0 + a1;
}

__global__ void __launch_bounds__(256, 1)
attractor_mma(const float* __restrict__ xg, const float* __restrict__ cg,
              const float* __restrict__ radg, float* __restrict__ out,
              int Brows, int write_idx)
{
    extern __shared__ char smraw[];
    const uint32_t sb = smem_u32(smraw);
    float* csq  = (float*)(smraw + O_CSQ);
    float* rad  = (float*)(smraw + O_RAD);
    unsigned long long* keyp = (unsigned long long*)(smraw + O_KEYP);
    float* csqp = (float*)(smraw + O_KEYP);   // setup-time reuse
    float* srow = (float*)(smraw + O_SROW);
    int*   jrow = (int*)(smraw + O_JROW);

    const int tid    = threadIdx.x;
    const int lane   = tid & 31;
    const int wid    = tid >> 5;
    const int warp_m = wid >> 2;   // 0..1 -> rows warp_m*64
    const int warp_n = wid & 3;    // 0..3 -> cols warp_n*32
    const int NT     = (Brows + 127) >> 7;

    if (tid < 128) rad[tid] = radg[tid];

    // ---- setup: convert c -> hi/mid bf16 planes (swizzled [n][k]) + csq ----
    {
        int n  = tid >> 1;
        int kh = tid & 1;                       // which 64-elem half of the row
        const float4* cp = reinterpret_cast<const float4*>(cg + n * EDIM + kh * 64);
        float acc = 0.f;
#pragma unroll
        for (int c8 = 0; c8 < 8; c8++) {        // 8 elems per 16B chunk
            float4 fa = cp[2 * c8], fb = cp[2 * c8 + 1];
            uint32_t h0 = cvt_hi2(fa.x, fa.y), h1 = cvt_hi2(fa.z, fa.w);
            uint32_t h2 = cvt_hi2(fb.x, fb.y), h3 = cvt_hi2(fb.z, fb.w);
            uint32_t m0 = cvt_mid2(fa.x, fa.y, h0), m1 = cvt_mid2(fa.z, fa.w, h1);
            uint32_t m2 = cvt_mid2(fb.x, fb.y, h2), m3 = cvt_mid2(fb.z, fb.w, h3);
            acc = fmaf(fa.x, fa.x, acc); acc = fmaf(fa.y, fa.y, acc);
            acc = fmaf(fa.z, fa.z, acc); acc = fmaf(fa.w, fa.w, acc);
            acc = fmaf(fb.x, fb.x, acc); acc = fmaf(fb.y, fb.y, acc);
            acc = fmaf(fb.z, fb.z, acc); acc = fmaf(fb.w, fb.w, acc);
            uint32_t kc = (uint32_t)(kh * 8 + c8);
            uint32_t o  = bswz((uint32_t)n, kc);
            *reinterpret_cast<uint4*>(smraw + B_HI  + o) = make_uint4(h0, h1, h2, h3);
            *reinterpret_cast<uint4*>(smraw + B_MID + o) = make_uint4(m0, m1, m2, m3);
        }
        csqp[tid] = acc;
    }
    __syncthreads();
    if (tid < 128) csq[tid] = csqp[2 * tid] + csqp[2 * tid + 1];
    __syncthreads();

    // ---- persistent tile loop ----
    for (int t = blockIdx.x; t < NT; t += gridDim.x) {
        const long long row0 = (long long)t << 7;

        float acc[4][4][4];
#pragma unroll
        for (int a = 0; a < 4; a++)
#pragma unroll
            for (int b = 0; b < 4; b++)
#pragma unroll
                for (int e = 0; e < 4; e++) acc[a][b][e] = 0.f;

        const int rbase = warp_m * 64 + (lane >> 2);
        const int kbase = (lane & 3) * 2;
        const uint32_t bn  = (uint32_t)(warp_n * 32 + (lane & 7));
        const uint32_t bm8 = (uint32_t)((lane >> 3) & 1);

#pragma unroll
        for (int ch = 0; ch < 8; ch++) {
            // B fragments for this k-chunk: 4 n-tiles x {hi, mid}
            uint32_t bh[4][2], bm[4][2];
            const uint32_t kc = (uint32_t)ch * 2 + bm8;
#pragma unroll
            for (int nt = 0; nt < 4; nt++) {
                uint32_t o = bswz(bn + (uint32_t)nt * 8, kc);
                ldm_x2(bh[nt][0], bh[nt][1], sb + B_HI  + o);
                ldm_x2(bm[nt][0], bm[nt][1], sb + B_MID + o);
            }
#pragma unroll
            for (int mt = 0; mt < 4; mt++) {
                const float* xp = xg + (row0 + rbase + mt * 16) * EDIM + ch * 16 + kbase;
                float2 p00 = *reinterpret_cast<const float2*>(xp);
                float2 p10 = *reinterpret_cast<const float2*>(xp + 8 * EDIM);
                float2 p01 = *reinterpret_cast<const float2*>(xp + 8);
                float2 p11 = *reinterpret_cast<const float2*>(xp + 8 * EDIM + 8);
                uint32_t ah[4], am[4];
                ah[0] = cvt_hi2(p00.x, p00.y); am[0] = cvt_mid2(p00.x, p00.y, ah[0]);
                ah[1] = cvt_hi2(p10.x, p10.y); am[1] = cvt_mid2(p10.x, p10.y, ah[1]);
                ah[2] = cvt_hi2(p01.x, p01.y); am[2] = cvt_mid2(p01.x, p01.y, ah[2]);
                ah[3] = cvt_hi2(p11.x, p11.y); am[3] = cvt_mid2(p11.x, p11.y, ah[3]);
#pragma unroll
                for (int nt = 0; nt < 4; nt++) {
                    mma16816(acc[mt][nt], ah, bh[nt]);
                    mma16816(acc[mt][nt], ah, bm[nt]);
                    mma16816(acc[mt][nt], am, bh[nt]);
                }
            }
        }

        // ---- per-row top-2 over this warp's 32 cols, then cross-warp merge ----
#pragma unroll
        for (int mt = 0; mt < 4; mt++) {
#pragma unroll
            for (int s = 0; s < 2; s++) {
                unsigned long long k1 = ~0ull, k2 = ~0ull;
#pragma unroll
                for (int nt = 0; nt < 4; nt++) {
#pragma unroll
                    for (int e = 0; e < 2; e++) {
                        int col = warp_n * 32 + nt * 8 + (lane & 3) * 2 + e;
                        float dot = acc[mt][nt][s * 2 + e];
                        float sc = fmaf(-2.f, dot, csq[col]);
                        unsigned long long kk =
                            ((unsigned long long)f2ord(sc) << 32) | (unsigned)col;
                        if (kk < k1) { k2 = k1; k1 = kk; }
                        else if (kk < k2) k2 = kk;
                    }
                }
#pragma unroll
                for (int m = 1; m < 4; m <<= 1) {
                    unsigned long long o1 = __shfl_xor_sync(0xffffffffu, k1, m);
                    unsigned long long o2 = __shfl_xor_sync(0xffffffffu, k2, m);
                    if (o1 < k1) { k2 = (k1 < o2) ? k1 : o2; k1 = o1; }
                    else         { k2 = (k2 < o1) ? k2 : o1; }
                }
                if ((lane & 3) == 0) {
                    int rloc = warp_m * 64 + mt * 16 + (lane >> 2) + s * 8;
                    keyp[(rloc * 4 + warp_n) * 2 + 0] = k1;
                    keyp[(rloc * 4 + warp_n) * 2 + 1] = k2;
                }
            }
        }
        __syncthreads();

        // ---- merge 4 warp-column results, exact d2, strength ----
        if (tid < 128) {
            unsigned long long g1 = ~0ull, g2 = ~0ull;
#pragma unroll
            for (int w = 0; w < 4; w++) {
                unsigned long long o1 = keyp[(tid * 4 + w) * 2 + 0];
                unsigned long long o2 = keyp[(tid * 4 + w) * 2 + 1];
                if (o1 < g1) { g2 = (g1 < o2) ? g1 : o2; g1 = o1; }
                else         { g2 = (g2 < o1) ? g2 : o1; }
            }
            int j = (int)(g1 & 0xFFFFFFFFull);
            long long rowg = row0 + tid;
            const float4* xp4 = reinterpret_cast<const float4*>(xg + rowg * EDIM);
            float d2a = exact_d2(xp4, reinterpret_cast<const float4*>(cg + (long long)j * EDIM));
            float s1 = ord2f_ok((uint32_t)(g1 >> 32));
            float s2 = ord2f_ok((uint32_t)(g2 >> 32));
            if (s2 - s1 < REFINE_T) {
                int jb = (int)(g2 & 0xFFFFFFFFull);
                float d2b = exact_d2(xp4, reinterpret_cast<const float4*>(cg + (long long)jb * EDIM));
                if (d2b < d2a || (d2b == d2a && jb < j)) { j = jb; d2a = d2b; }
            }
            float dist = sqrtf(fmaxf(d2a, 0.f));
            float strength = expf(-dist / (rad[j] + 1e-8f));
            srow[tid] = 0.1f * strength;
            jrow[tid] = j;
            if (write_idx && rowg < Brows)
                out[(long long)Brows * EDIM + rowg] = (float)j;
        }
        __syncthreads();

        // ---- attracted = x*(1-s) + c[j]*s ----
        {
            int rloc = tid >> 1, half = tid & 1;
            long long rowg = row0 + rloc;
            float s = srow[rloc];
            int j = jrow[rloc];
            float om = 1.f - s;
            const float4* xp4 = reinterpret_cast<const float4*>(xg + rowg * EDIM + half * 64);
            const float4* cp4 = reinterpret_cast<const float4*>(cg + (long long)j * EDIM + half * 64);
            float4* op4 = reinterpret_cast<float4*>(out + rowg * EDIM + half * 64);
#pragma unroll
            for (int q = 0; q < 16; q++) {
                float4 xv = xp4[q], cv = cp4[q];
                float4 o;
                o.x = fmaf(cv.x, s, xv.x * om);
                o.y = fmaf(cv.y, s, xv.y * om);
                o.z = fmaf(cv.z, s, xv.z * om);
                o.w = fmaf(cv.w, s, xv.w * om);
                op4[q] = o;
            }
        }
        __syncthreads();
    }
}

extern "C" void kernel_launch(void* const* d_in, const int* in_sizes, int n_in,
                              void* d_out, int out_size)
{
    const float* x     = (const float*)d_in[0];
    const float* c     = (const float*)d_in[1];
    const float* radii = (const float*)d_in[2];
    float* out = (float*)d_out;

    int Brows = in_sizes[0] / EDIM;
    int write_idx = (out_size >= Brows * (EDIM + 1)) ? 1 : 0;

    int sms = 148;
    cudaDeviceGetAttribute(&sms, cudaDevAttrMultiProcessorCount, 0);
    int nt = (Brows + 127) / 128;
    int grid = sms < nt ? sms : nt;

    cudaFuncSetAttribute(attractor_mma,
                         cudaFuncAttributeMaxDynamicSharedMemorySize, (int)SMEM_TOTAL);
    attractor_mma<<<grid, 256, SMEM_TOTAL>>>(x, c, radii, out, Brows, write_idx);
}

// round 5
// speedup vs baseline: 2.8114x; 1.4981x over previous
#include <cuda_runtime.h>
#include <cuda_bf16.h>
#include <cstdint>
#include <math.h>

#define EDIM 128
#define NTH  512

// ---- dynamic smem byte offsets ----
#define B_HI   0u        // c hi plane  [n=128][k=128] bf16 swizzled
#define B_MID  32768u    // c mid plane
#define A_HI   65536u    // x hi plane  [m=128][k=128]
#define A_MID  98304u    // x mid plane
#define O_CSQ  131072u   // float[128]
#define O_RAD  131584u   // float[128]
#define O_XSQ  132096u   // float[128]
#define O_XSQP 132608u   // float[128][4] partials (reused for csq setup)
#define O_KEYP 134656u   // u64[128][4][2]
#define O_SROW 142848u   // float[128]
#define O_JROW 143360u   // int[128]
#define SMEM_TOTAL 143872u

#define REFINE_T 1e-2f

__device__ __forceinline__ uint32_t smem_u32(const void* p) {
    uint32_t a;
    asm("{ .reg .u64 t; cvta.to.shared.u64 t, %1; cvt.u32.u64 %0, t; }" : "=r"(a) : "l"(p));
    return a;
}
// swizzled byte offset of 16B chunk kc (0..15) in row n of a [128 rows][256B] plane
__device__ __forceinline__ uint32_t bswz(uint32_t n, uint32_t kc) {
    return n * 256u + ((((kc ^ n) & 7u) | (kc & 8u)) << 4);
}
__device__ __forceinline__ uint32_t cvt_hi2(float lo, float hi) {
    uint32_t r;
    asm("cvt.rn.bf16x2.f32 %0, %1, %2;" : "=r"(r) : "f"(hi), "f"(lo));
    return r;
}
__device__ __forceinline__ uint32_t cvt_mid2(float lo, float hi, uint32_t h) {
    float hlo = __uint_as_float(h << 16);
    float hhi = __uint_as_float(h & 0xFFFF0000u);
    return cvt_hi2(lo - hlo, hi - hhi);
}
__device__ __forceinline__ void ldm_x2(uint32_t& r0, uint32_t& r1, uint32_t addr) {
    asm volatile("ldmatrix.sync.aligned.m8n8.x2.shared.b16 {%0,%1}, [%2];"
                 : "=r"(r0), "=r"(r1) : "r"(addr));
}
__device__ __forceinline__ void ldm_x4(uint32_t* r, uint32_t addr) {
    asm volatile("ldmatrix.sync.aligned.m8n8.x4.shared.b16 {%0,%1,%2,%3}, [%4];"
                 : "=r"(r[0]), "=r"(r[1]), "=r"(r[2]), "=r"(r[3]) : "r"(addr));
}
__device__ __forceinline__ void mma16816(float* d, const uint32_t* a, const uint32_t* b) {
    asm volatile("mma.sync.aligned.m16n8k16.row.col.f32.bf16.bf16.f32 "
                 "{%0,%1,%2,%3}, {%4,%5,%6,%7}, {%8,%9}, {%0,%1,%2,%3};"
                 : "+f"(d[0]), "+f"(d[1]), "+f"(d[2]), "+f"(d[3])
                 : "r"(a[0]), "r"(a[1]), "r"(a[2]), "r"(a[3]), "r"(b[0]), "r"(b[1]));
}
__device__ __forceinline__ uint32_t f2ord(float f) {
    uint32_t u = __float_as_uint(f);
    return (u & 0x80000000u) ? ~u : (u | 0x80000000u);
}
__device__ __forceinline__ float ord2f(uint32_t o) {
    uint32_t u = (o & 0x80000000u) ? (o ^ 0x80000000u) : ~o;
    return __uint_as_float(u);
}
__device__ __forceinline__ float blo(uint32_t w) { return __uint_as_float(w << 16); }
__device__ __forceinline__ float bhi(uint32_t w) { return __uint_as_float(w & 0xFFFF0000u); }
__device__ __forceinline__ float2 rec2(uint32_t h, uint32_t m) {
    return make_float2(blo(h) + blo(m), bhi(h) + bhi(m));
}
__device__ __forceinline__ float exact_d2(const float4* __restrict__ xp,
                                          const float4* __restrict__ cp) {
    float a0 = 0.f, a1 = 0.f;
#pragma unroll 8
    for (int q = 0; q < 32; q++) {
        float4 xv = __ldg(xp + q), cv = __ldg(cp + q);
        float t0 = xv.x - cv.x, t1 = xv.y - cv.y;
        float t2 = xv.z - cv.z, t3 = xv.w - cv.w;
        a0 = fmaf(t0, t0, a0); a1 = fmaf(t1, t1, a1);
        a0 = fmaf(t2, t2, a0); a1 = fmaf(t3, t3, a1);
    }
    return a0 + a1;
}
// convert 16B chunk (8 floats) -> hi/mid planes at plane_hi (+32768 for mid)
__device__ __forceinline__ float cvt_chunk(char* sm, uint32_t plane_hi, uint32_t n,
                                           uint32_t kc, const float4& fa,
                                           const float4& fb, float acc) {
    uint32_t h0 = cvt_hi2(fa.x, fa.y), h1 = cvt_hi2(fa.z, fa.w);
    uint32_t h2 = cvt_hi2(fb.x, fb.y), h3 = cvt_hi2(fb.z, fb.w);
    uint32_t m0 = cvt_mid2(fa.x, fa.y, h0), m1 = cvt_mid2(fa.z, fa.w, h1);
    uint32_t m2 = cvt_mid2(fb.x, fb.y, h2), m3 = cvt_mid2(fb.z, fb.w, h3);
    acc = fmaf(fa.x, fa.x, acc); acc = fmaf(fa.y, fa.y, acc);
    acc = fmaf(fa.z, fa.z, acc); acc = fmaf(fa.w, fa.w, acc);
    acc = fmaf(fb.x, fb.x, acc); acc = fmaf(fb.y, fb.y, acc);
    acc = fmaf(fb.z, fb.z, acc); acc = fmaf(fb.w, fb.w, acc);
    uint32_t o = bswz(n, kc);
    *reinterpret_cast<uint4*>(sm + plane_hi + o)          = make_uint4(h0, h1, h2, h3);
    *reinterpret_cast<uint4*>(sm + plane_hi + 32768u + o) = make_uint4(m0, m1, m2, m3);
    return acc;
}

__global__ void __launch_bounds__(NTH, 1)
attractor_mma2(const float* __restrict__ xg, const float* __restrict__ cg,
               const float* __restrict__ radg, float* __restrict__ out,
               int Brows, int write_idx)
{
    extern __shared__ char smraw[];
    const uint32_t sb = smem_u32(smraw);
    float* csq  = (float*)(smraw + O_CSQ);
    float* rad  = (float*)(smraw + O_RAD);
    float* xsq  = (float*)(smraw + O_XSQ);
    float* prt  = (float*)(smraw + O_XSQP);
    unsigned long long* keyp = (unsigned long long*)(smraw + O_KEYP);
    float* srow = (float*)(smraw + O_SROW);
    int*   jrow = (int*)(smraw + O_JROW);

    const int tid    = threadIdx.x;
    const int lane   = tid & 31;
    const int wid    = tid >> 5;
    const int warp_m = wid >> 2;   // 0..3 -> rows warp_m*32
    const int warp_n = wid & 3;    // 0..3 -> cols warp_n*32
    const int NT     = (Brows + 127) >> 7;

    if (tid < 128) rad[tid] = radg[tid];

    // ---- setup: convert c -> B planes + csq ----
    {
        int n = tid >> 2, q = tid & 3;
        const float4* cp = reinterpret_cast<const float4*>(cg + n * EDIM + q * 32);
        float acc = 0.f;
#pragma unroll
        for (int i = 0; i < 4; i++)
            acc = cvt_chunk(smraw, B_HI, (uint32_t)n, (uint32_t)(q * 4 + i),
                            cp[2 * i], cp[2 * i + 1], acc);
        prt[tid] = acc;
    }
    __syncthreads();
    if (tid < 128)
        csq[tid] = prt[4 * tid] + prt[4 * tid + 1] + prt[4 * tid + 2] + prt[4 * tid + 3];
    __syncthreads();

    // lane-invariant fragment address parts
    const uint32_t arow = (uint32_t)(warp_m * 32 + (lane & 15));
    const uint32_t akh  = (uint32_t)(lane >> 4);          // k-half for A ldmatrix.x4
    const uint32_t bnr  = (uint32_t)(warp_n * 32 + (lane & 7));
    const uint32_t bkh  = (uint32_t)((lane >> 3) & 1);    // k-half for B ldmatrix.x2

    // ---- persistent tile loop ----
    for (int t = blockIdx.x; t < NT; t += gridDim.x) {
        const long long row0 = (long long)t << 7;

        // convert x tile -> A planes + xsq partials
        {
            int r = tid >> 2, q = tid & 3;
            long long rowg = row0 + r;
            if (rowg >= Brows) rowg = Brows - 1;
            const float4* xp = reinterpret_cast<const float4*>(xg + rowg * EDIM + q * 32);
            float acc = 0.f;
#pragma unroll
            for (int i = 0; i < 4; i++)
                acc = cvt_chunk(smraw, A_HI, (uint32_t)r, (uint32_t)(q * 4 + i),
                                xp[2 * i], xp[2 * i + 1], acc);
            prt[tid] = acc;
        }
        __syncthreads();
        if (tid < 128)
            xsq[tid] = prt[4 * tid] + prt[4 * tid + 1] + prt[4 * tid + 2] + prt[4 * tid + 3];

        // ---- MMA mainloop: warp tile 32x32, 3 split passes ----
        float acc[2][4][4];
#pragma unroll
        for (int a = 0; a < 2; a++)
#pragma unroll
            for (int b = 0; b < 4; b++)
#pragma unroll
                for (int e = 0; e < 4; e++) acc[a][b][e] = 0.f;

#pragma unroll
        for (int ch = 0; ch < 8; ch++) {
            uint32_t ah[2][4], am[2][4];
            const uint32_t akc = (uint32_t)ch * 2 + akh;
#pragma unroll
            for (int mt = 0; mt < 2; mt++) {
                uint32_t o = bswz(arow + (uint32_t)mt * 16, akc);
                ldm_x4(ah[mt], sb + A_HI + o);
                ldm_x4(am[mt], sb + A_MID + o);
            }
            uint32_t bh[4][2], bm[4][2];
            const uint32_t bkc = (uint32_t)ch * 2 + bkh;
#pragma unroll
            for (int nt = 0; nt < 4; nt++) {
                uint32_t o = bswz(bnr + (uint32_t)nt * 8, bkc);
                ldm_x2(bh[nt][0], bh[nt][1], sb + B_HI + o);
                ldm_x2(bm[nt][0], bm[nt][1], sb + B_MID + o);
            }
#pragma unroll
            for (int mt = 0; mt < 2; mt++)
#pragma unroll
                for (int nt = 0; nt < 4; nt++) {
                    mma16816(acc[mt][nt], ah[mt], bh[nt]);
                    mma16816(acc[mt][nt], ah[mt], bm[nt]);
                    mma16816(acc[mt][nt], am[mt], bh[nt]);
                }
        }

        // ---- per-row top-2 over this warp's 32 cols ----
#pragma unroll
        for (int mt = 0; mt < 2; mt++) {
#pragma unroll
            for (int s = 0; s < 2; s++) {
                unsigned long long k1 = ~0ull, k2 = ~0ull;
#pragma unroll
                for (int nt = 0; nt < 4; nt++) {
#pragma unroll
                    for (int e = 0; e < 2; e++) {
                        int col = warp_n * 32 + nt * 8 + (lane & 3) * 2 + e;
                        float sc = fmaf(-2.f, acc[mt][nt][s * 2 + e], csq[col]);
                        unsigned long long kk =
                            ((unsigned long long)f2ord(sc) << 32) | (unsigned)col;
                        if (kk < k1) { k2 = k1; k1 = kk; }
                        else if (kk < k2) k2 = kk;
                    }
                }
#pragma unroll
                for (int m = 1; m < 4; m <<= 1) {
                    unsigned long long o1 = __shfl_xor_sync(0xffffffffu, k1, m);
                    unsigned long long o2 = __shfl_xor_sync(0xffffffffu, k2, m);
                    if (o1 < k1) { k2 = (k1 < o2) ? k1 : o2; k1 = o1; }
                    else         { k2 = (k2 < o1) ? k2 : o1; }
                }
                if ((lane & 3) == 0) {
                    int rloc = warp_m * 32 + mt * 16 + (lane >> 2) + s * 8;
                    keyp[(rloc * 4 + warp_n) * 2 + 0] = k1;
                    keyp[(rloc * 4 + warp_n) * 2 + 1] = k2;
                }
            }
        }
        __syncthreads();

        // ---- merge 4 warp-column results; refine only tight rows ----
        if (tid < 128) {
            unsigned long long g1 = ~0ull, g2 = ~0ull;
#pragma unroll
            for (int w = 0; w < 4; w++) {
                unsigned long long o1 = keyp[(tid * 4 + w) * 2 + 0];
                unsigned long long o2 = keyp[(tid * 4 + w) * 2 + 1];
                if (o1 < g1) { g2 = (g1 < o2) ? g1 : o2; g1 = o1; }
                else         { g2 = (g2 < o1) ? g2 : o1; }
            }
            int j = (int)(g1 & 0xFFFFFFFFull);
            long long rowg = row0 + tid;
            float s1 = ord2f((uint32_t)(g1 >> 32));
            float s2 = ord2f((uint32_t)(g2 >> 32));
            float d2;
            if (s2 - s1 < REFINE_T && rowg < Brows) {
                const float4* xp4 = reinterpret_cast<const float4*>(xg + rowg * EDIM);
                int jb = (int)(g2 & 0xFFFFFFFFull);
                float d2a = exact_d2(xp4, reinterpret_cast<const float4*>(cg + (long long)j * EDIM));
                float d2b = exact_d2(xp4, reinterpret_cast<const float4*>(cg + (long long)jb * EDIM));
                if (d2b < d2a || (d2b == d2a && jb < j)) { j = jb; d2a = d2b; }
                d2 = d2a;
            } else {
                d2 = xsq[tid] + s1;
            }
            float dist = sqrtf(fmaxf(d2, 0.f));
            float strength = expf(-dist / (rad[j] + 1e-8f));
            srow[tid] = 0.1f * strength;
            jrow[tid] = j;
            if (write_idx && rowg < Brows)
                out[(long long)Brows * EDIM + rowg] = (float)j;
        }
        __syncthreads();

        // ---- output: attracted = x*(1-s) + c[j]*s, reconstructed from smem planes ----
        {
            int r = tid >> 2, q = tid & 3;
            long long rowg = row0 + r;
            if (rowg < Brows) {
                float s = srow[r];
                int j = jrow[r];
                float om = 1.f - s;
                float4* op = reinterpret_cast<float4*>(out + rowg * EDIM + q * 32);
#pragma unroll
                for (int i = 0; i < 4; i++) {
                    uint32_t ox = bswz((uint32_t)r, (uint32_t)(q * 4 + i));
                    uint32_t oc = bswz((uint32_t)j, (uint32_t)(q * 4 + i));
                    uint4 xh = *reinterpret_cast<uint4*>(smraw + A_HI + ox);
                    uint4 xm = *reinterpret_cast<uint4*>(smraw + A_MID + ox);
                    uint4 chv = *reinterpret_cast<uint4*>(smraw + B_HI + oc);
                    uint4 cmv = *reinterpret_cast<uint4*>(smraw + B_MID + oc);
                    float2 x0 = rec2(xh.x, xm.x), x1 = rec2(xh.y, xm.y);
                    float2 x2 = rec2(xh.z, xm.z), x3 = rec2(xh.w, xm.w);
                    float2 c0 = rec2(chv.x, cmv.x), c1 = rec2(chv.y, cmv.y);
                    float2 c2 = rec2(chv.z, cmv.z), c3 = rec2(chv.w, cmv.w);
                    float4 o0, o1;
                    o0.x = fmaf(c0.x, s, x0.x * om); o0.y = fmaf(c0.y, s, x0.y * om);
                    o0.z = fmaf(c1.x, s, x1.x * om); o0.w = fmaf(c1.y, s, x1.y * om);
                    o1.x = fmaf(c2.x, s, x2.x * om); o1.y = fmaf(c2.y, s, x2.y * om);
                    o1.z = fmaf(c3.x, s, x3.x * om); o1.w = fmaf(c3.y, s, x3.y * om);
                    op[2 * i]     = o0;
                    op[2 * i + 1] = o1;
                }
            }
        }
        __syncthreads();   // A planes free for next tile's convert
    }
}

extern "C" void kernel_launch(void* const* d_in, const int* in_sizes, int n_in,
                              void* d_out, int out_size)
{
    const float* x     = (const float*)d_in[0];
    const float* c     = (const float*)d_in[1];
    const float* radii = (const float*)d_in[2];
    float* out = (float*)d_out;

    int Brows = in_sizes[0] / EDIM;
    int write_idx = (out_size >= Brows * (EDIM + 1)) ? 1 : 0;

    int sms = 148;
    cudaDeviceGetAttribute(&sms, cudaDevAttrMultiProcessorCount, 0);
    int nt = (Brows + 127) / 128;
    int grid = sms < nt ? sms : nt;

    cudaFuncSetAttribute(attractor_mma2,
                         cudaFuncAttributeMaxDynamicSharedMemorySize, (int)SMEM_TOTAL);
    attractor_mma2<<<grid, NTH, SMEM_TOTAL>>>(x, c, radii, out, Brows, write_idx);
}